// round 16
// baseline (speedup 1.0000x reference)
#include <cuda_runtime.h>
#include <cstdint>

// Problem constants
#define B_ROWS   65536
#define N_SPARSE 26
#define VOCAB    5000
#define N_DENSE  13

#define THREADS     1024
#define ROWS_PB     444       // 444*104B = 46176B, 16B-aligned per block
#define NBLOCKS     148       // last block: 268 rows; grid divisible by cluster
#define CLUSTER     2
#define CHUNK_ROWS  112
#define N_CHUNKS    4

#define N_CACHED 18           // features [0,18) via smem; [18,26) + crosses direct
#define PASS_NF  3
#define N_PASSES 6
#define NBUF     3            // each buffer reused exactly once

// Dynamic smem layout (bytes), 16B-aligned
#define BUF_BYTES   (PASS_NF * VOCAB * 4)       // 60000
#define HALF_BYTES  (BUF_BYTES / 2)             // 30000 (16B mult)
#define IDX_OFF     (NBUF * BUF_BYTES)          // 180000
#define IDX_BYTES   (ROWS_PB * N_SPARSE * 4)    // 46176
#define MBAR_OFF    (IDX_OFF + IDX_BYTES)       // 226176
// barriers: 4 io + 3 full + 3 consumed = 10 x 8B
#define SMEM_TOTAL  (MBAR_OFF + 10 * 8)         // 226256 (< 232448 max dyn smem)

__device__ __forceinline__ uint32_t smem_u32(const void* p) {
    return (uint32_t)__cvta_generic_to_shared(p);
}
__device__ __forceinline__ void mbar_init(uint32_t mbar, uint32_t count) {
    asm volatile("mbarrier.init.shared.b64 [%0], %1;" :: "r"(mbar), "r"(count) : "memory");
}
__device__ __forceinline__ void mbar_expect_tx(uint32_t mbar, uint32_t bytes) {
    asm volatile("mbarrier.arrive.expect_tx.shared.b64 _, [%0], %1;"
                 :: "r"(mbar), "r"(bytes) : "memory");
}
__device__ __forceinline__ void mbar_wait(uint32_t mbar, uint32_t parity) {
    uint32_t done = 0;
    while (!done) {
        asm volatile(
            "{\n\t.reg .pred p;\n\t"
            "mbarrier.try_wait.parity.acquire.cta.shared::cta.b64 p, [%1], %2, 0x989680;\n\t"
            "selp.b32 %0, 1, 0, p;\n\t}"
            : "=r"(done) : "r"(mbar), "r"(parity) : "memory");
    }
}
__device__ __forceinline__ void bulk_g2s(uint32_t dst, const void* src,
                                         uint32_t bytes, uint32_t mbar) {
    asm volatile(
        "cp.async.bulk.shared::cta.global.mbarrier::complete_tx::bytes [%0], [%1], %2, [%3];"
        :: "r"(dst), "l"(src), "r"(bytes), "r"(mbar) : "memory");
}
// Multicast bulk copy: delivers bytes + complete_tx to the same smem offset in
// every CTA of the cluster whose bit is set in mask.
__device__ __forceinline__ void bulk_g2s_mc(uint32_t dst, const void* src,
                                            uint32_t bytes, uint32_t mbar,
                                            uint16_t mask) {
    asm volatile(
        "cp.async.bulk.shared::cluster.global.mbarrier::complete_tx::bytes.multicast::cluster "
        "[%0], [%1], %2, [%3], %4;"
        :: "r"(dst), "l"(src), "r"(bytes), "r"(mbar), "h"(mask) : "memory");
}
__device__ __forceinline__ void mbar_arrive_peer(uint32_t local_mbar, uint32_t peer) {
    asm volatile(
        "{\n\t.reg .b32 r;\n\t"
        "mapa.shared::cluster.u32 r, %0, %1;\n\t"
        "mbarrier.arrive.shared::cluster.b64 _, [r];\n\t}"
        :: "r"(local_mbar), "r"(peer) : "memory");
}
__device__ __forceinline__ uint32_t ctarank() {
    uint32_t r;
    asm("mov.u32 %0, %%cluster_ctarank;" : "=r"(r));
    return r;
}
#define CLUSTER_SYNC() do { \
    asm volatile("barrier.cluster.arrive.aligned;" ::: "memory"); \
    asm volatile("barrier.cluster.wait.aligned;"   ::: "memory"); \
} while (0)

__global__ __launch_bounds__(THREADS, 1) __cluster_dims__(CLUSTER, 1, 1)
void wide_kernel(
    const float* __restrict__ dense,        // [B, 13]
    const float* __restrict__ emb_table,    // [26, 5000]
    const float* __restrict__ cross_table0, // [25e6]
    const float* __restrict__ cross_table1, // [25e6]
    const float* __restrict__ dense_w,      // [13]
    const int*   __restrict__ sparse_idx,   // [B, 26] int32
    float*       __restrict__ out)          // [B]
{
    extern __shared__ __align__(16) char smem[];
    int* s_idx = (int*)(smem + IDX_OFF);

    const uint32_t mb_io0  = smem_u32(smem + MBAR_OFF);            // 4 io chunks
    const uint32_t mb_full = smem_u32(smem + MBAR_OFF + 32);       // 3 slice-full
    const uint32_t mb_cons = smem_u32(smem + MBAR_OFF + 56);       // 3 consumed
    const uint32_t buf0_s  = smem_u32(smem);

    const int tid  = threadIdx.x;
    const int row0 = blockIdx.x * ROWS_PB;
    const int rows = min(ROWS_PB, B_ROWS - row0);
    const uint32_t rank = ctarank();
    const uint32_t peer = rank ^ 1;

    if (tid == 0) {
        #pragma unroll
        for (int c = 0; c < N_CHUNKS; c++) mbar_init(mb_io0 + 8 * c, 1);
        #pragma unroll
        for (int s = 0; s < NBUF; s++) {
            mbar_init(mb_full + 8 * s, 1);
            mbar_init(mb_cons + 8 * s, 1);   // one arrival: the peer CTA
        }
    }
    __syncthreads();

    // Local idx chunks can start before the cluster is synced.
    if (tid == 0) {
        #pragma unroll
        for (int c = 0; c < N_CHUNKS; c++) {
            const int crow0 = c * CHUNK_ROWS;
            const int crows = max(0, min(CHUNK_ROWS, rows - crow0));
            const uint32_t ib = (uint32_t)crows * N_SPARSE * 4;
            mbar_expect_tx(mb_io0 + 8 * c, ib);   // 0 bytes -> flips immediately
            if (crows > 0) {
                bulk_g2s(smem_u32(s_idx + crow0 * N_SPARSE),
                         sparse_idx + (size_t)(row0 + crow0) * N_SPARSE, ib, mb_io0 + 8 * c);
            }
        }
    }

    // Peer mbarriers must be initialized before any multicast targets them.
    CLUSTER_SYNC();

    // Each CTA issues only its HALF of slices 0..2; multicast delivers both
    // halves to both CTAs. expect_tx counts the full slice per CTA.
    if (tid == 0) {
        #pragma unroll
        for (int s = 0; s < NBUF; s++) {
            mbar_expect_tx(mb_full + 8 * s, BUF_BYTES);
            bulk_g2s_mc(buf0_s + s * BUF_BYTES + rank * HALF_BYTES,
                        emb_table + s * PASS_NF * VOCAB + rank * (HALF_BYTES / 4),
                        HALF_BYTES, mb_full + 8 * s, (uint16_t)0x3);
        }
    }

    const int  sub    = tid & 1;             // 2 sub-threads per row
    const int  rawrow = tid >> 1;
    const bool active = (rawrow < rows);

    // Wait only for this thread's own idx chunk.
    const int chunk = min(rawrow / CHUNK_ROWS, N_CHUNKS - 1);
    mbar_wait(mb_io0 + 8 * chunk, 0);

    const int* my = &s_idx[rawrow * N_SPARSE];
    float acc = 0.0f;

    if (active) {
        if (sub == 0) {
            acc += __ldg(&cross_table0[my[0] * VOCAB + my[1]]);     // DRAM first
            #pragma unroll
            for (int f = N_CACHED; f < 22; f++)                     // 18..21
                acc += __ldg(&emb_table[f * VOCAB + my[f]]);
        } else {
            acc += __ldg(&cross_table1[my[2] * VOCAB + my[3]]);
            #pragma unroll
            for (int f = 22; f < N_SPARSE; f++)                     // 22..25
                acc += __ldg(&emb_table[f * VOCAB + my[f]]);
        }

        // Dense dot straight from gmem (contiguous, coalesced across adjacent
        // rows), pair-split (7 / 6).
        const float* dr = &dense[(size_t)(row0 + rawrow) * N_DENSE];
        if (sub == 0) {
            #pragma unroll
            for (int d = 0; d < 7; d++) acc += __ldg(&dr[d]) * __ldg(&dense_w[d]);
        } else {
            #pragma unroll
            for (int d = 7; d < N_DENSE; d++) acc += __ldg(&dr[d]) * __ldg(&dense_w[d]);
        }
    }

    // 6 passes x 3 features over [0, 18); 3 buffers, each recycled once.
    #pragma unroll
    for (int p = 0; p < N_PASSES; p++) {
        const int b = p % NBUF;
        mbar_wait(mb_full + 8 * b, (p < NBUF) ? 0 : 1);

        if (active) {
            const float* tb = (const float*)(smem + b * BUF_BYTES);
            const int f0 = p * PASS_NF;
            // Balance across the pair: one sub takes 2 features, other takes 1.
            if (sub == (p & 1)) {
                acc += tb[0 * VOCAB + my[f0 + 0]];
                acc += tb[1 * VOCAB + my[f0 + 1]];
            } else {
                acc += tb[2 * VOCAB + my[f0 + 2]];
            }
        }

        __syncthreads();   // this CTA's consumers done with buffer b

        if (p < NBUF && tid == 0) {
            // Tell peer we're done with buffer b; wait until peer is too
            // (peer's reissue writes into OUR smem via multicast).
            mbar_arrive_peer(mb_cons + 8 * b, peer);
            mbar_wait(mb_cons + 8 * b, 0);
            // Reissue slice p+3 into buffer b (our half, multicast to both).
            mbar_expect_tx(mb_full + 8 * b, BUF_BYTES);
            bulk_g2s_mc(buf0_s + b * BUF_BYTES + rank * HALF_BYTES,
                        emb_table + (p + NBUF) * PASS_NF * VOCAB + rank * (HALF_BYTES / 4),
                        HALF_BYTES, mb_full + 8 * b, (uint16_t)0x3);
        }
    }

    // Pair combine + store
    acc += __shfl_xor_sync(0xFFFFFFFFu, acc, 1);
    if (active && sub == 0) out[row0 + rawrow] = acc;

    // No CTA exits while a peer multicast targeting its smem may be in flight.
    CLUSTER_SYNC();
}

extern "C" void kernel_launch(void* const* d_in, const int* in_sizes, int n_in,
                              void* d_out, int out_size)
{
    const float* dense        = nullptr;
    const float* emb_table    = nullptr;
    const float* cross_table0 = nullptr;
    const float* cross_table1 = nullptr;
    const float* dense_w      = nullptr;
    const int*   sparse_idx   = nullptr;

    for (int i = 0; i < n_in; i++) {
        const long long sz = in_sizes[i];
        if      (sz == (long long)B_ROWS * N_DENSE)   dense      = (const float*)d_in[i];
        else if (sz == (long long)N_SPARSE * VOCAB)   emb_table  = (const float*)d_in[i];
        else if (sz == (long long)VOCAB * VOCAB) {
            if (!cross_table0) cross_table0 = (const float*)d_in[i];
            else               cross_table1 = (const float*)d_in[i];
        }
        else if (sz == N_DENSE)                       dense_w    = (const float*)d_in[i];
        else if (sz == (long long)B_ROWS * N_SPARSE)  sparse_idx = (const int*)d_in[i];
    }

    float* out = (float*)d_out;

    static bool attr_set = false;
    if (!attr_set) {
        cudaFuncSetAttribute(wide_kernel,
                             cudaFuncAttributeMaxDynamicSharedMemorySize, SMEM_TOTAL);
        attr_set = true;
    }

    wide_kernel<<<NBLOCKS, THREADS, SMEM_TOTAL>>>(dense, emb_table,
                                                  cross_table0, cross_table1,
                                                  dense_w, sparse_idx, out);
}